// round 16
// baseline (speedup 1.0000x reference)
#include <cuda_runtime.h>
#include <math.h>

#define BATCH 128
#define TIME  4096
#define T0    2048
#define T1    1024
#define T2    512
#define C0    32
#define C1    64
#define C2    128
#define HID   256
#define G3H   768
#define RMS_EPS 1e-6f

// ---------------- scratch (device globals; no runtime allocation) -------
__device__ float g_h0[(size_t)BATCH * T0 * C0];
__device__ float g_h1[(size_t)BATCH * T1 * C1];
__device__ float g_h2[(size_t)BATCH * T2 * C2];
__device__ float g_xi[(size_t)BATCH * T2 * G3H];
__device__ float g_hseq[(size_t)BATCH * T2 * HID];
__device__ float g_wn[HID * HID];

__device__ __forceinline__ float gelu_tanh(float x) {
    float u = 0.7978845608028654f * (x + 0.044715f * x * x * x);
    return 0.5f * x * (1.0f + tanhf(u));
}
__device__ __forceinline__ float sigm(float x) { return 1.0f / (1.0f + expf(-x)); }

// ---- packed f32x2 helpers (Blackwell) ----
__device__ __forceinline__ unsigned long long pk2(float lo, float hi) {
    unsigned long long d;
    asm("mov.b64 %0, {%1, %2};" : "=l"(d)
        : "r"(__float_as_uint(lo)), "r"(__float_as_uint(hi)));
    return d;
}
__device__ __forceinline__ unsigned long long f2fma(unsigned long long a,
                                                    unsigned long long b,
                                                    unsigned long long c) {
    unsigned long long d;
    asm("fma.rn.f32x2 %0, %1, %2, %3;" : "=l"(d) : "l"(a), "l"(b), "l"(c));
    return d;
}
__device__ __forceinline__ float2 upk(unsigned long long v) {
    unsigned lo, hi;
    asm("mov.b64 {%0, %1}, %2;" : "=r"(lo), "=r"(hi) : "l"(v));
    float2 r; r.x = __uint_as_float(lo); r.y = __uint_as_float(hi);
    return r;
}

// ======================= prep: weight-normalized proj matrix ============
__global__ void k_wnorm(const float* __restrict__ v, const float* __restrict__ g) {
    int j = threadIdx.x;
    float ss = 0.f;
    for (int k = 0; k < HID; k++) { float t = v[k * HID + j]; ss = fmaf(t, t, ss); }
    float inv = g[j] / (sqrtf(ss) + 1e-8f);
    for (int k = 0; k < HID; k++) g_wn[k * HID + j] = v[k * HID + j] * inv;
}

// ======================= conv0: [128,4096] -> [128,2048,32] =============
__global__ void k_conv0(const float* __restrict__ x, const float* __restrict__ w,
                        const float* __restrict__ bias, const float* __restrict__ scale) {
    __shared__ float w_s[9 * C0];
    __shared__ float b_s[C0], s_s[C0];
    int tid = threadIdx.x;
    for (int i = tid; i < 9 * C0; i += 256) w_s[i] = w[i];
    if (tid < C0) { b_s[tid] = bias[tid]; s_s[tid] = scale[tid]; }
    __syncthreads();

    int b = blockIdx.y;
    int t = blockIdx.x * 256 + tid;
    const float* xrow = x + (size_t)b * TIME;
    float xv[9];
    int base = 2 * t - 3;
#pragma unroll
    for (int k = 0; k < 9; k++) {
        int p = base + k;
        xv[k] = (p >= 0 && p < TIME) ? xrow[p] * 1e20f : 0.0f;
    }
    float acc[C0];
#pragma unroll
    for (int c = 0; c < C0; c++) acc[c] = b_s[c];
#pragma unroll
    for (int k = 0; k < 9; k++) {
        float xk = xv[k];
#pragma unroll
        for (int c = 0; c < C0; c++) acc[c] = fmaf(xk, w_s[k * C0 + c], acc[c]);
    }
    float ss = 0.f;
#pragma unroll
    for (int c = 0; c < C0; c++) ss = fmaf(acc[c], acc[c], ss);
    float rs = rsqrtf(ss * (1.0f / C0) + RMS_EPS);
    float* orow = g_h0 + ((size_t)b * T0 + t) * C0;
#pragma unroll
    for (int c = 0; c < C0; c++) orow[c] = gelu_tanh(acc[c] * rs * s_s[c]);
}

// ======================= conv1: [128,2048,32] -> [128,1024,64] ==========
__global__ void k_conv1(const float* __restrict__ w, const float* __restrict__ bias,
                        const float* __restrict__ scale) {
    __shared__ float in_s[71][C0];
    __shared__ float4 wk[C0 * C1 / 4];
    __shared__ float b_s[C1], s_s[C1];
    int tid = threadIdx.x;
    int b = blockIdx.y, t0 = blockIdx.x * 32;
    int base = 2 * t0 - 3;
    for (int i = tid; i < 71 * C0; i += 256) {
        int pl = i >> 5, ci = i & 31;
        int p = base + pl;
        in_s[pl][ci] = (p >= 0 && p < T0) ? g_h0[((size_t)b * T0 + p) * C0 + ci] : 0.0f;
    }
    if (tid < C1) { b_s[tid] = bias[tid]; s_s[tid] = scale[tid]; }

    int cg = tid & 15, tg = tid >> 4;
    float acc[2][4] = {};
    for (int k = 0; k < 9; k++) {
        __syncthreads();
        const float4* ws = (const float4*)(w + (size_t)k * C0 * C1);
        for (int i = tid; i < C0 * C1 / 4; i += 256) wk[i] = ws[i];
        __syncthreads();
#pragma unroll 8
        for (int ci = 0; ci < C0; ci++) {
            float4 wv = wk[ci * 16 + cg];
#pragma unroll
            for (int i = 0; i < 2; i++) {
                float xv = in_s[2 * (tg * 2 + i) + k][ci];
                acc[i][0] = fmaf(xv, wv.x, acc[i][0]);
                acc[i][1] = fmaf(xv, wv.y, acc[i][1]);
                acc[i][2] = fmaf(xv, wv.z, acc[i][2]);
                acc[i][3] = fmaf(xv, wv.w, acc[i][3]);
            }
        }
    }
#pragma unroll
    for (int i = 0; i < 2; i++) {
        float ss = 0.f;
#pragma unroll
        for (int j = 0; j < 4; j++) { acc[i][j] += b_s[cg * 4 + j]; ss = fmaf(acc[i][j], acc[i][j], ss); }
        ss += __shfl_xor_sync(0xffffffffu, ss, 1);
        ss += __shfl_xor_sync(0xffffffffu, ss, 2);
        ss += __shfl_xor_sync(0xffffffffu, ss, 4);
        ss += __shfl_xor_sync(0xffffffffu, ss, 8);
        float rs = rsqrtf(ss * (1.0f / C1) + RMS_EPS);
        int t = t0 + tg * 2 + i;
        float4 o;
        o.x = gelu_tanh(acc[i][0] * rs * s_s[cg * 4 + 0]);
        o.y = gelu_tanh(acc[i][1] * rs * s_s[cg * 4 + 1]);
        o.z = gelu_tanh(acc[i][2] * rs * s_s[cg * 4 + 2]);
        o.w = gelu_tanh(acc[i][3] * rs * s_s[cg * 4 + 3]);
        *(float4*)&g_h1[((size_t)b * T1 + t) * C1 + cg * 4] = o;
    }
}

// ======================= conv2: 32-t tile, 4 CTAs/SM =====================
// smem: in_s[71][65] (4616 pad) + wk[64][128] + b/s = 52256 B
#define C2_INS 4616
#define CONV2_SMEM ((C2_INS + 64 * 128 + 256) * 4)
__global__ void k_conv2(const float* __restrict__ w, const float* __restrict__ bias,
                        const float* __restrict__ scale) {
    extern __shared__ __align__(16) float cs2[];
    float* in_s = cs2;                      // [71][65]
    float* wk   = cs2 + C2_INS;             // [64][128], 16B aligned
    float* b_s  = wk + 64 * 128;
    float* s_s  = b_s + 128;
    int tid = threadIdx.x;
    int b = blockIdx.y, t0 = blockIdx.x * 32;
    int base = 2 * t0 - 3;
    for (int i = tid; i < 71 * C1; i += 256) {
        int pl = i >> 6, ci = i & 63;
        int p = base + pl;
        in_s[pl * 65 + ci] = (p >= 0 && p < T1) ? g_h1[((size_t)b * T1 + p) * C1 + ci] : 0.0f;
    }
    if (tid < C2) { b_s[tid] = bias[tid]; s_s[tid] = scale[tid]; }

    int wrp = tid >> 5, lane = tid & 31;
    int cg = lane & 15, trow = lane >> 4;
    int co0 = cg * 8;
    int tl0 = wrp * 4 + trow * 2;
    unsigned long long acc[2][4];
#pragma unroll
    for (int i = 0; i < 2; i++)
#pragma unroll
        for (int j = 0; j < 4; j++) acc[i][j] = 0ULL;

    for (int k = 0; k < 9; k++) {
        __syncthreads();
        for (int i = tid; i < C1 * C2; i += 256) wk[i] = w[(size_t)k * C1 * C2 + i];
        __syncthreads();
#pragma unroll 4
        for (int ci = 0; ci < C1; ci++) {
            ulonglong2 w01 = *(const ulonglong2*)&wk[ci * C2 + co0];
            ulonglong2 w23 = *(const ulonglong2*)&wk[ci * C2 + co0 + 4];
#pragma unroll
            for (int i = 0; i < 2; i++) {
                float xv = in_s[(2 * (tl0 + i) + k) * 65 + ci];
                unsigned long long xd = pk2(xv, xv);
                acc[i][0] = f2fma(w01.x, xd, acc[i][0]);
                acc[i][1] = f2fma(w01.y, xd, acc[i][1]);
                acc[i][2] = f2fma(w23.x, xd, acc[i][2]);
                acc[i][3] = f2fma(w23.y, xd, acc[i][3]);
            }
        }
    }
#pragma unroll
    for (int i = 0; i < 2; i++) {
        float o[8];
        float ss = 0.f;
#pragma unroll
        for (int jp = 0; jp < 4; jp++) {
            float2 v = upk(acc[i][jp]);
            o[2 * jp]     = v.x + b_s[co0 + 2 * jp];
            o[2 * jp + 1] = v.y + b_s[co0 + 2 * jp + 1];
            ss = fmaf(o[2 * jp], o[2 * jp], ss);
            ss = fmaf(o[2 * jp + 1], o[2 * jp + 1], ss);
        }
        ss += __shfl_xor_sync(0xffffffffu, ss, 1);
        ss += __shfl_xor_sync(0xffffffffu, ss, 2);
        ss += __shfl_xor_sync(0xffffffffu, ss, 4);
        ss += __shfl_xor_sync(0xffffffffu, ss, 8);
        float rs = rsqrtf(ss * (1.0f / C2) + RMS_EPS);
        int t = t0 + tl0 + i;
        float4 q0, q1;
        q0.x = gelu_tanh(o[0] * rs * s_s[co0 + 0]);
        q0.y = gelu_tanh(o[1] * rs * s_s[co0 + 1]);
        q0.z = gelu_tanh(o[2] * rs * s_s[co0 + 2]);
        q0.w = gelu_tanh(o[3] * rs * s_s[co0 + 3]);
        q1.x = gelu_tanh(o[4] * rs * s_s[co0 + 4]);
        q1.y = gelu_tanh(o[5] * rs * s_s[co0 + 5]);
        q1.z = gelu_tanh(o[6] * rs * s_s[co0 + 6]);
        q1.w = gelu_tanh(o[7] * rs * s_s[co0 + 7]);
        float* orow = &g_h2[((size_t)b * T2 + t) * C2 + co0];
        *(float4*)orow = q0;
        *(float4*)(orow + 4) = q1;
    }
}

// ======================= xi GEMM: [65536,128] @ [128,768] + bi ==========
__global__ void k_xi(const float* __restrict__ wi, const float* __restrict__ bi) {
    __shared__ float a_s[64][65];
    __shared__ float b_s[64][64];
    int tid = threadIdx.x;
    int m0 = blockIdx.x * 64, n0 = blockIdx.y * 64;
    int tx = tid & 15, ty = tid >> 4;
    float acc[4][4] = {};
    for (int kc = 0; kc < 128; kc += 64) {
        __syncthreads();
        for (int i = tid; i < 4096; i += 256) {
            int r = i >> 6, c = i & 63;
            a_s[r][c] = g_h2[(size_t)(m0 + r) * C2 + kc + c];
            b_s[r][c] = wi[(size_t)(kc + r) * G3H + n0 + c];
        }
        __syncthreads();
#pragma unroll 8
        for (int k = 0; k < 64; k++) {
            float a[4], bb[4];
#pragma unroll
            for (int i = 0; i < 4; i++) a[i] = a_s[ty + 16 * i][k];
#pragma unroll
            for (int j = 0; j < 4; j++) bb[j] = b_s[k][tx + 16 * j];
#pragma unroll
            for (int i = 0; i < 4; i++)
#pragma unroll
                for (int j = 0; j < 4; j++) acc[i][j] = fmaf(a[i], bb[j], acc[i][j]);
        }
    }
#pragma unroll
    for (int i = 0; i < 4; i++)
#pragma unroll
        for (int j = 0; j < 4; j++)
            g_xi[(size_t)(m0 + ty + 16 * i) * G3H + n0 + tx + 16 * j] = acc[i][j] + bi[n0 + tx + 16 * j];
}

// ======================= GRU: 4-CTA cluster, j-packed k-loop ============
#define GRU_THREADS 384
#define GRU_SMEM (196608 + 8256 + 12288)

__global__ void __cluster_dims__(4, 1, 1) __launch_bounds__(GRU_THREADS, 1)
k_gru(const float* __restrict__ wh, const float* __restrict__ bhn) {
    extern __shared__ float smem[];
    float*  w_s  = smem;                         // [g][k][j]: g*16384 + k*64 + j
    float2* h_s  = (float2*)(smem + 49152);      // [buf][pair][k]: buf*516 + pair*258 + k
    float2* part = h_s + 1032;                   // [12 slices][4 rows][64 j] floats

    unsigned rank;
    asm("mov.u32 %0, %%cluster_ctarank;" : "=r"(rank));
    int tid = threadIdx.x;
    int cid = blockIdx.x >> 2;
    int r0  = cid * 4;
    int jg0 = (int)rank * 64;

    for (int i = tid; i < 3 * 256 * 64; i += GRU_THREADS) {
        int g = i >> 14, rem = i & 16383;
        int k = rem >> 6, j = rem & 63;
        w_s[i] = wh[(size_t)k * G3H + g * HID + jg0 + j];
    }
    for (int i = tid; i < 516; i += GRU_THREADS) h_s[i] = make_float2(0.f, 0.f);
    __syncthreads();
    asm volatile("barrier.cluster.arrive.aligned;" ::: "memory");
    asm volatile("barrier.cluster.wait.aligned;"   ::: "memory");

    int wid = tid >> 5, lane = tid & 31;
    int g = wid >> 2, ks = wid & 3;
    int pair = lane >> 4, jq = lane & 15;
    const float* wbase = w_s + g * 16384 + (ks * 64) * 64 + jq * 4;

    int erow = tid >> 6, ej = tid & 63;
    int epair = erow >> 1, ehalf = erow & 1;
    bool epi = (tid < 256);
    float ebhn = 0.f;
    const float* xi_p = nullptr;
    float* o_p = nullptr;
    if (epi) {
        ebhn = bhn[jg0 + ej];
        xi_p = g_xi + (size_t)(r0 + erow) * T2 * G3H;
        o_p  = g_hseq + (size_t)(r0 + erow) * T2 * HID + jg0 + ej;
    }
    unsigned hbase_local;
    {
        unsigned a;
        asm("{ .reg .u64 t; cvta.to.shared.u64 t, %1; cvt.u32.u64 %0, t; }"
            : "=r"(a) : "l"((void*)h_s));
        hbase_local = a + (unsigned)((epair * 258 + jg0 + ej) * 8 + ehalf * 4);
    }
    unsigned maddr[4];
#pragma unroll
    for (int rr = 0; rr < 4; rr++)
        asm("mapa.shared::cluster.u32 %0, %1, %2;" : "=r"(maddr[rr]) : "r"(hbase_local), "r"(rr));

    float hprev = 0.f;
    int buf = 0;
    unsigned long long* pf = (unsigned long long*)part;
    int pbase = ((g * 4 + ks) * 4 + 2 * pair) * 32 + jq * 2;
    const float* paf = (const float*)part;

    // preload xi[0] (subsequent steps prefetched in barrier shadow)
    float xr = 0.f, xz = 0.f, xn = 0.f;
    if (epi) {
        const float* p = xi_p + jg0 + ej;
        xr = __ldg(p); xz = __ldg(p + HID); xn = __ldg(p + 2 * HID);
    }

    for (int t = 0; t < T2; t++) {
        // j-packed matvec slice: LDS.128 weights = 2 ready f32x2 operands
        unsigned long long a00 = 0, a01 = 0, a10 = 0, a11 = 0;
        const float2* hb = h_s + buf * 516 + pair * 258 + ks * 64;
        const float* wp = wbase;
#pragma unroll 8
        for (int kk = 0; kk < 64; kk++) {
            float2 hp = hb[kk];
            unsigned long long h0 = pk2(hp.x, hp.x);
            unsigned long long h1 = pk2(hp.y, hp.y);
            ulonglong2 wv = *(const ulonglong2*)wp;
            wp += 64;
            a00 = f2fma(wv.x, h0, a00);
            a01 = f2fma(wv.y, h0, a01);
            a10 = f2fma(wv.x, h1, a10);
            a11 = f2fma(wv.y, h1, a11);
        }
        pf[pbase]      = a00;   // row 2*pair,   j(jq*4 + 0,1)
        pf[pbase + 1]  = a01;   // row 2*pair,   j(jq*4 + 2,3)
        pf[pbase + 32] = a10;   // row 2*pair+1
        pf[pbase + 33] = a11;
        __syncthreads();

        if (epi) {
            float hr = 0.f, hz = 0.f, hn = 0.f;
#pragma unroll
            for (int s = 0; s < 4; s++) {
                hr += paf[((0 + s) * 4 + erow) * 64 + ej];
                hz += paf[((4 + s) * 4 + erow) * 64 + ej];
                hn += paf[((8 + s) * 4 + erow) * 64 + ej];
            }
            float r = sigm(xr + hr);
            float z = sigm(xz + hz);
            float n = tanhf(xn + r * (hn + ebhn));
            float hnew = (1.f - z) * n + z * hprev;
            hprev = hnew;
            o_p[(size_t)t * HID] = hnew;
            unsigned boff = (unsigned)((buf ^ 1) * 4128);   // 516 float2 = 4128 B
#pragma unroll
            for (int rr = 0; rr < 4; rr++)
                asm volatile("st.shared::cluster.f32 [%0], %1;"
                             :: "r"(maddr[rr] + boff), "f"(hnew) : "memory");
        }
        asm volatile("barrier.cluster.arrive.aligned;" ::: "memory");
        // prefetch next xi while the cluster barrier drains
        if (epi && t + 1 < T2) {
            const float* p = xi_p + (size_t)(t + 1) * G3H + jg0 + ej;
            xr = __ldg(p); xz = __ldg(p + HID); xn = __ldg(p + 2 * HID);
        }
        asm volatile("barrier.cluster.wait.aligned;"   ::: "memory");
        buf ^= 1;
    }
}

// ======================= proj GEMM + bias + row L2-norm =================
__global__ void k_proj(const float* __restrict__ pb, float* __restrict__ out) {
    __shared__ float a_s[32][33];
    __shared__ float b_s[32][HID];
    int tid = threadIdx.x;
    int m0 = blockIdx.x * 32;
    int cg = tid & 31, rg = tid >> 5;
    float acc[4][8] = {};
    for (int kc = 0; kc < HID; kc += 32) {
        __syncthreads();
        for (int i = tid; i < 32 * 32; i += 256) {
            int r = i >> 5, c = i & 31;
            a_s[r][c] = g_hseq[(size_t)(m0 + r) * HID + kc + c];
        }
        for (int i = tid; i < 32 * HID; i += 256) {
            int r = i >> 8, c = i & 255;
            b_s[r][c] = g_wn[(size_t)(kc + r) * HID + c];
        }
        __syncthreads();
#pragma unroll 4
        for (int k = 0; k < 32; k++) {
            float a[4], bb[8];
#pragma unroll
            for (int i = 0; i < 4; i++) a[i] = a_s[rg * 4 + i][k];
#pragma unroll
            for (int j = 0; j < 8; j++) bb[j] = b_s[k][cg + 32 * j];
#pragma unroll
            for (int i = 0; i < 4; i++)
#pragma unroll
                for (int j = 0; j < 8; j++) acc[i][j] = fmaf(a[i], bb[j], acc[i][j]);
        }
    }
#pragma unroll
    for (int i = 0; i < 4; i++) {
        float ss = 0.f;
#pragma unroll
        for (int j = 0; j < 8; j++) {
            acc[i][j] += pb[cg + 32 * j];
            ss = fmaf(acc[i][j], acc[i][j], ss);
        }
        ss += __shfl_xor_sync(0xffffffffu, ss, 1);
        ss += __shfl_xor_sync(0xffffffffu, ss, 2);
        ss += __shfl_xor_sync(0xffffffffu, ss, 4);
        ss += __shfl_xor_sync(0xffffffffu, ss, 8);
        ss += __shfl_xor_sync(0xffffffffu, ss, 16);
        float nrm = sqrtf(ss);
        float sc = (nrm > 1e-6f) ? 1.0f / (nrm + 1e-8f) : 1.0f;
        size_t row = (size_t)(m0 + rg * 4 + i);
#pragma unroll
        for (int j = 0; j < 8; j++) out[row * HID + cg + 32 * j] = acc[i][j] * sc;
    }
}

// ======================= launcher =======================================
extern "C" void kernel_launch(void* const* d_in, const int* in_sizes, int n_in,
                              void* d_out, int out_size) {
    (void)in_sizes; (void)n_in; (void)out_size;
    const float* x   = (const float*)d_in[0];
    const float* c0w = (const float*)d_in[1];
    const float* c0b = (const float*)d_in[2];
    const float* r0s = (const float*)d_in[3];
    const float* c1w = (const float*)d_in[4];
    const float* c1b = (const float*)d_in[5];
    const float* r1s = (const float*)d_in[6];
    const float* c2w = (const float*)d_in[7];
    const float* c2b = (const float*)d_in[8];
    const float* r2s = (const float*)d_in[9];
    const float* wi  = (const float*)d_in[10];
    const float* bi  = (const float*)d_in[11];
    const float* wh  = (const float*)d_in[12];
    const float* bhn = (const float*)d_in[13];
    const float* pv  = (const float*)d_in[14];
    const float* pg  = (const float*)d_in[15];
    const float* pb  = (const float*)d_in[16];
    float* out = (float*)d_out;

    cudaFuncSetAttribute(k_gru, cudaFuncAttributeMaxDynamicSharedMemorySize, GRU_SMEM);
    cudaFuncSetAttribute(k_conv2, cudaFuncAttributeMaxDynamicSharedMemorySize, CONV2_SMEM);

    k_wnorm<<<1, 256>>>(pv, pg);
    k_conv0<<<dim3(8, BATCH), 256>>>(x, c0w, c0b, r0s);
    k_conv1<<<dim3(32, BATCH), 256>>>(c1w, c1b, r1s);
    k_conv2<<<dim3(16, BATCH), 256, CONV2_SMEM>>>(c2w, c2b, r2s);
    k_xi<<<dim3(1024, 12), 256>>>(wi, bi);
    k_gru<<<128, GRU_THREADS, GRU_SMEM>>>(wh, bhn);
    k_proj<<<2048, 256>>>(pb, out);
}

// round 17
// speedup vs baseline: 1.0944x; 1.0944x over previous
#include <cuda_runtime.h>
#include <math.h>

#define BATCH 128
#define TIME  4096
#define T0    2048
#define T1    1024
#define T2    512
#define C0    32
#define C1    64
#define C2    128
#define HID   256
#define G3H   768
#define RMS_EPS 1e-6f

// ---------------- scratch (device globals; no runtime allocation) -------
__device__ float g_h0[(size_t)BATCH * T0 * C0];
__device__ float g_h1[(size_t)BATCH * T1 * C1];
__device__ float g_h2[(size_t)BATCH * T2 * C2];
__device__ float g_xi[(size_t)BATCH * T2 * G3H];
__device__ float g_hseq[(size_t)BATCH * T2 * HID];
__device__ float g_wn[HID * HID];

__device__ __forceinline__ float gelu_tanh(float x) {
    float u = 0.7978845608028654f * (x + 0.044715f * x * x * x);
    return 0.5f * x * (1.0f + tanhf(u));
}
__device__ __forceinline__ float sigm(float x) { return 1.0f / (1.0f + expf(-x)); }

// ---- packed f32x2 helpers (Blackwell) ----
__device__ __forceinline__ unsigned long long pk2(float lo, float hi) {
    unsigned long long d;
    asm("mov.b64 %0, {%1, %2};" : "=l"(d)
        : "r"(__float_as_uint(lo)), "r"(__float_as_uint(hi)));
    return d;
}
__device__ __forceinline__ unsigned long long f2fma(unsigned long long a,
                                                    unsigned long long b,
                                                    unsigned long long c) {
    unsigned long long d;
    asm("fma.rn.f32x2 %0, %1, %2, %3;" : "=l"(d) : "l"(a), "l"(b), "l"(c));
    return d;
}
__device__ __forceinline__ float2 upk(unsigned long long v) {
    unsigned lo, hi;
    asm("mov.b64 {%0, %1}, %2;" : "=r"(lo), "=r"(hi) : "l"(v));
    float2 r; r.x = __uint_as_float(lo); r.y = __uint_as_float(hi);
    return r;
}

// ======================= prep: weight-normalized proj matrix ============
__global__ void k_wnorm(const float* __restrict__ v, const float* __restrict__ g) {
    int j = threadIdx.x;
    float ss = 0.f;
    for (int k = 0; k < HID; k++) { float t = v[k * HID + j]; ss = fmaf(t, t, ss); }
    float inv = g[j] / (sqrtf(ss) + 1e-8f);
    for (int k = 0; k < HID; k++) g_wn[k * HID + j] = v[k * HID + j] * inv;
}

// ======================= conv0: [128,4096] -> [128,2048,32] =============
__global__ void k_conv0(const float* __restrict__ x, const float* __restrict__ w,
                        const float* __restrict__ bias, const float* __restrict__ scale) {
    __shared__ float w_s[9 * C0];
    __shared__ float b_s[C0], s_s[C0];
    int tid = threadIdx.x;
    for (int i = tid; i < 9 * C0; i += 256) w_s[i] = w[i];
    if (tid < C0) { b_s[tid] = bias[tid]; s_s[tid] = scale[tid]; }
    __syncthreads();

    int b = blockIdx.y;
    int t = blockIdx.x * 256 + tid;
    const float* xrow = x + (size_t)b * TIME;
    float xv[9];
    int base = 2 * t - 3;
#pragma unroll
    for (int k = 0; k < 9; k++) {
        int p = base + k;
        xv[k] = (p >= 0 && p < TIME) ? xrow[p] * 1e20f : 0.0f;
    }
    float acc[C0];
#pragma unroll
    for (int c = 0; c < C0; c++) acc[c] = b_s[c];
#pragma unroll
    for (int k = 0; k < 9; k++) {
        float xk = xv[k];
#pragma unroll
        for (int c = 0; c < C0; c++) acc[c] = fmaf(xk, w_s[k * C0 + c], acc[c]);
    }
    float ss = 0.f;
#pragma unroll
    for (int c = 0; c < C0; c++) ss = fmaf(acc[c], acc[c], ss);
    float rs = rsqrtf(ss * (1.0f / C0) + RMS_EPS);
    float* orow = g_h0 + ((size_t)b * T0 + t) * C0;
#pragma unroll
    for (int c = 0; c < C0; c++) orow[c] = gelu_tanh(acc[c] * rs * s_s[c]);
}

// ======================= conv1: [128,2048,32] -> [128,1024,64] ==========
__global__ void k_conv1(const float* __restrict__ w, const float* __restrict__ bias,
                        const float* __restrict__ scale) {
    __shared__ float in_s[71][C0];
    __shared__ float4 wk[C0 * C1 / 4];
    __shared__ float b_s[C1], s_s[C1];
    int tid = threadIdx.x;
    int b = blockIdx.y, t0 = blockIdx.x * 32;
    int base = 2 * t0 - 3;
    for (int i = tid; i < 71 * C0; i += 256) {
        int pl = i >> 5, ci = i & 31;
        int p = base + pl;
        in_s[pl][ci] = (p >= 0 && p < T0) ? g_h0[((size_t)b * T0 + p) * C0 + ci] : 0.0f;
    }
    if (tid < C1) { b_s[tid] = bias[tid]; s_s[tid] = scale[tid]; }

    int cg = tid & 15, tg = tid >> 4;
    float acc[2][4] = {};
    for (int k = 0; k < 9; k++) {
        __syncthreads();
        const float4* ws = (const float4*)(w + (size_t)k * C0 * C1);
        for (int i = tid; i < C0 * C1 / 4; i += 256) wk[i] = ws[i];
        __syncthreads();
#pragma unroll 8
        for (int ci = 0; ci < C0; ci++) {
            float4 wv = wk[ci * 16 + cg];
#pragma unroll
            for (int i = 0; i < 2; i++) {
                float xv = in_s[2 * (tg * 2 + i) + k][ci];
                acc[i][0] = fmaf(xv, wv.x, acc[i][0]);
                acc[i][1] = fmaf(xv, wv.y, acc[i][1]);
                acc[i][2] = fmaf(xv, wv.z, acc[i][2]);
                acc[i][3] = fmaf(xv, wv.w, acc[i][3]);
            }
        }
    }
#pragma unroll
    for (int i = 0; i < 2; i++) {
        float ss = 0.f;
#pragma unroll
        for (int j = 0; j < 4; j++) { acc[i][j] += b_s[cg * 4 + j]; ss = fmaf(acc[i][j], acc[i][j], ss); }
        ss += __shfl_xor_sync(0xffffffffu, ss, 1);
        ss += __shfl_xor_sync(0xffffffffu, ss, 2);
        ss += __shfl_xor_sync(0xffffffffu, ss, 4);
        ss += __shfl_xor_sync(0xffffffffu, ss, 8);
        float rs = rsqrtf(ss * (1.0f / C1) + RMS_EPS);
        int t = t0 + tg * 2 + i;
        float4 o;
        o.x = gelu_tanh(acc[i][0] * rs * s_s[cg * 4 + 0]);
        o.y = gelu_tanh(acc[i][1] * rs * s_s[cg * 4 + 1]);
        o.z = gelu_tanh(acc[i][2] * rs * s_s[cg * 4 + 2]);
        o.w = gelu_tanh(acc[i][3] * rs * s_s[cg * 4 + 3]);
        *(float4*)&g_h1[((size_t)b * T1 + t) * C1 + cg * 4] = o;
    }
}

// ======================= conv2 (R9/R13 retile, measured 360us) ==========
#define IN_S_PAD 8776
#define CONV2_SMEM ((IN_S_PAD + 64 * 128 + 256) * 4)
__global__ void k_conv2(const float* __restrict__ w, const float* __restrict__ bias,
                        const float* __restrict__ scale) {
    extern __shared__ __align__(16) float cs2[];
    float* in_s = cs2;                      // [135][65]
    float* wk   = cs2 + IN_S_PAD;           // [64][128], 16B aligned
    float* b_s  = wk + 64 * 128;
    float* s_s  = b_s + 128;
    int tid = threadIdx.x;
    int b = blockIdx.y, t0 = blockIdx.x * 64;
    int base = 2 * t0 - 3;
    for (int i = tid; i < 135 * C1; i += 256) {
        int pl = i >> 6, ci = i & 63;
        int p = base + pl;
        in_s[pl * 65 + ci] = (p >= 0 && p < T1) ? g_h1[((size_t)b * T1 + p) * C1 + ci] : 0.0f;
    }
    if (tid < C2) { b_s[tid] = bias[tid]; s_s[tid] = scale[tid]; }

    int wrp = tid >> 5, lane = tid & 31;
    int cg = lane & 15, trow = lane >> 4;
    int co0 = cg * 8;
    int tl0 = wrp * 8 + trow * 4;
    unsigned long long acc[4][4];
#pragma unroll
    for (int i = 0; i < 4; i++)
#pragma unroll
        for (int j = 0; j < 4; j++) acc[i][j] = 0ULL;

    for (int k = 0; k < 9; k++) {
        __syncthreads();
        for (int i = tid; i < C1 * C2; i += 256) wk[i] = w[(size_t)k * C1 * C2 + i];
        __syncthreads();
#pragma unroll 4
        for (int ci = 0; ci < C1; ci++) {
            ulonglong2 w01 = *(const ulonglong2*)&wk[ci * C2 + co0];
            ulonglong2 w23 = *(const ulonglong2*)&wk[ci * C2 + co0 + 4];
#pragma unroll
            for (int i = 0; i < 4; i++) {
                float xv = in_s[(2 * (tl0 + i) + k) * 65 + ci];
                unsigned long long xd = pk2(xv, xv);
                acc[i][0] = f2fma(w01.x, xd, acc[i][0]);
                acc[i][1] = f2fma(w01.y, xd, acc[i][1]);
                acc[i][2] = f2fma(w23.x, xd, acc[i][2]);
                acc[i][3] = f2fma(w23.y, xd, acc[i][3]);
            }
        }
    }
#pragma unroll
    for (int i = 0; i < 4; i++) {
        float o[8];
        float ss = 0.f;
#pragma unroll
        for (int jp = 0; jp < 4; jp++) {
            float2 v = upk(acc[i][jp]);
            o[2 * jp]     = v.x + b_s[co0 + 2 * jp];
            o[2 * jp + 1] = v.y + b_s[co0 + 2 * jp + 1];
            ss = fmaf(o[2 * jp], o[2 * jp], ss);
            ss = fmaf(o[2 * jp + 1], o[2 * jp + 1], ss);
        }
        ss += __shfl_xor_sync(0xffffffffu, ss, 1);
        ss += __shfl_xor_sync(0xffffffffu, ss, 2);
        ss += __shfl_xor_sync(0xffffffffu, ss, 4);
        ss += __shfl_xor_sync(0xffffffffu, ss, 8);
        float rs = rsqrtf(ss * (1.0f / C2) + RMS_EPS);
        int t = t0 + tl0 + i;
        float4 q0, q1;
        q0.x = gelu_tanh(o[0] * rs * s_s[co0 + 0]);
        q0.y = gelu_tanh(o[1] * rs * s_s[co0 + 1]);
        q0.z = gelu_tanh(o[2] * rs * s_s[co0 + 2]);
        q0.w = gelu_tanh(o[3] * rs * s_s[co0 + 3]);
        q1.x = gelu_tanh(o[4] * rs * s_s[co0 + 4]);
        q1.y = gelu_tanh(o[5] * rs * s_s[co0 + 5]);
        q1.z = gelu_tanh(o[6] * rs * s_s[co0 + 6]);
        q1.w = gelu_tanh(o[7] * rs * s_s[co0 + 7]);
        float* orow = &g_h2[((size_t)b * T2 + t) * C2 + co0];
        *(float4*)orow = q0;
        *(float4*)(orow + 4) = q1;
    }
}

// ======================= xi GEMM: [65536,128] @ [128,768] + bi ==========
__global__ void k_xi(const float* __restrict__ wi, const float* __restrict__ bi) {
    __shared__ float a_s[64][65];
    __shared__ float b_s[64][64];
    int tid = threadIdx.x;
    int m0 = blockIdx.x * 64, n0 = blockIdx.y * 64;
    int tx = tid & 15, ty = tid >> 4;
    float acc[4][4] = {};
    for (int kc = 0; kc < 128; kc += 64) {
        __syncthreads();
        for (int i = tid; i < 4096; i += 256) {
            int r = i >> 6, c = i & 63;
            a_s[r][c] = g_h2[(size_t)(m0 + r) * C2 + kc + c];
            b_s[r][c] = wi[(size_t)(kc + r) * G3H + n0 + c];
        }
        __syncthreads();
#pragma unroll 8
        for (int k = 0; k < 64; k++) {
            float a[4], bb[4];
#pragma unroll
            for (int i = 0; i < 4; i++) a[i] = a_s[ty + 16 * i][k];
#pragma unroll
            for (int j = 0; j < 4; j++) bb[j] = b_s[k][tx + 16 * j];
#pragma unroll
            for (int i = 0; i < 4; i++)
#pragma unroll
                for (int j = 0; j < 4; j++) acc[i][j] = fmaf(a[i], bb[j], acc[i][j]);
        }
    }
#pragma unroll
    for (int i = 0; i < 4; i++)
#pragma unroll
        for (int j = 0; j < 4; j++)
            g_xi[(size_t)(m0 + ty + 16 * i) * G3H + n0 + tx + 16 * j] = acc[i][j] + bi[n0 + tx + 16 * j];
}

// ======================= GRU: 4-CTA cluster, j-packed k-loop ============
#define GRU_THREADS 384
#define GRU_SMEM (196608 + 8256 + 12288)

__global__ void __cluster_dims__(4, 1, 1) __launch_bounds__(GRU_THREADS, 1)
k_gru(const float* __restrict__ wh, const float* __restrict__ bhn) {
    extern __shared__ float smem[];
    float*  w_s  = smem;                         // [g][k][j]: g*16384 + k*64 + j
    float2* h_s  = (float2*)(smem + 49152);      // [buf][pair][k]: buf*516 + pair*258 + k
    float2* part = h_s + 1032;                   // [12 slices][4 rows][64 j] floats

    unsigned rank;
    asm("mov.u32 %0, %%cluster_ctarank;" : "=r"(rank));
    int tid = threadIdx.x;
    int cid = blockIdx.x >> 2;
    int r0  = cid * 4;
    int jg0 = (int)rank * 64;

    for (int i = tid; i < 3 * 256 * 64; i += GRU_THREADS) {
        int g = i >> 14, rem = i & 16383;
        int k = rem >> 6, j = rem & 63;
        w_s[i] = wh[(size_t)k * G3H + g * HID + jg0 + j];
    }
    for (int i = tid; i < 516; i += GRU_THREADS) h_s[i] = make_float2(0.f, 0.f);
    __syncthreads();
    asm volatile("barrier.cluster.arrive.aligned;" ::: "memory");
    asm volatile("barrier.cluster.wait.aligned;"   ::: "memory");

    int wid = tid >> 5, lane = tid & 31;
    int g = wid >> 2, ks = wid & 3;
    int pair = lane >> 4, jq = lane & 15;
    const float* wbase = w_s + g * 16384 + (ks * 64) * 64 + jq * 4;

    int erow = tid >> 6, ej = tid & 63;
    int epair = erow >> 1, ehalf = erow & 1;
    bool epi = (tid < 256);
    float ebhn = 0.f;
    const float* xi_p = nullptr;
    float* o_p = nullptr;
    if (epi) {
        ebhn = bhn[jg0 + ej];
        xi_p = g_xi + (size_t)(r0 + erow) * T2 * G3H;
        o_p  = g_hseq + (size_t)(r0 + erow) * T2 * HID + jg0 + ej;
    }
    unsigned hbase_local;
    {
        unsigned a;
        asm("{ .reg .u64 t; cvta.to.shared.u64 t, %1; cvt.u32.u64 %0, t; }"
            : "=r"(a) : "l"((void*)h_s));
        hbase_local = a + (unsigned)((epair * 258 + jg0 + ej) * 8 + ehalf * 4);
    }
    unsigned maddr[4];
#pragma unroll
    for (int rr = 0; rr < 4; rr++)
        asm("mapa.shared::cluster.u32 %0, %1, %2;" : "=r"(maddr[rr]) : "r"(hbase_local), "r"(rr));

    float hprev = 0.f;
    int buf = 0;
    unsigned long long* pf = (unsigned long long*)part;
    int pbase = ((g * 4 + ks) * 4 + 2 * pair) * 32 + jq * 2;
    const float* paf = (const float*)part;

    // preload xi[0] (subsequent steps prefetched in barrier shadow)
    float xr = 0.f, xz = 0.f, xn = 0.f;
    if (epi) {
        const float* p = xi_p + jg0 + ej;
        xr = __ldg(p); xz = __ldg(p + HID); xn = __ldg(p + 2 * HID);
    }

    for (int t = 0; t < T2; t++) {
        // j-packed matvec slice: LDS.128 weights = 2 ready f32x2 operands
        unsigned long long a00 = 0, a01 = 0, a10 = 0, a11 = 0;
        const float2* hb = h_s + buf * 516 + pair * 258 + ks * 64;
        const float* wp = wbase;
#pragma unroll 8
        for (int kk = 0; kk < 64; kk++) {
            float2 hp = hb[kk];
            unsigned long long h0 = pk2(hp.x, hp.x);
            unsigned long long h1 = pk2(hp.y, hp.y);
            ulonglong2 wv = *(const ulonglong2*)wp;
            wp += 64;
            a00 = f2fma(wv.x, h0, a00);
            a01 = f2fma(wv.y, h0, a01);
            a10 = f2fma(wv.x, h1, a10);
            a11 = f2fma(wv.y, h1, a11);
        }
        pf[pbase]      = a00;   // row 2*pair,   j(jq*4 + 0,1)
        pf[pbase + 1]  = a01;   // row 2*pair,   j(jq*4 + 2,3)
        pf[pbase + 32] = a10;   // row 2*pair+1
        pf[pbase + 33] = a11;
        __syncthreads();

        if (epi) {
            float hr = 0.f, hz = 0.f, hn = 0.f;
#pragma unroll
            for (int s = 0; s < 4; s++) {
                hr += paf[((0 + s) * 4 + erow) * 64 + ej];
                hz += paf[((4 + s) * 4 + erow) * 64 + ej];
                hn += paf[((8 + s) * 4 + erow) * 64 + ej];
            }
            float r = sigm(xr + hr);
            float z = sigm(xz + hz);
            float n = tanhf(xn + r * (hn + ebhn));
            float hnew = (1.f - z) * n + z * hprev;
            hprev = hnew;
            o_p[(size_t)t * HID] = hnew;
            unsigned boff = (unsigned)((buf ^ 1) * 4128);   // 516 float2 = 4128 B
#pragma unroll
            for (int rr = 0; rr < 4; rr++)
                asm volatile("st.shared::cluster.f32 [%0], %1;"
                             :: "r"(maddr[rr] + boff), "f"(hnew) : "memory");
        }
        asm volatile("barrier.cluster.arrive.aligned;" ::: "memory");
        // prefetch next xi while the cluster barrier drains
        if (epi && t + 1 < T2) {
            const float* p = xi_p + (size_t)(t + 1) * G3H + jg0 + ej;
            xr = __ldg(p); xz = __ldg(p + HID); xn = __ldg(p + 2 * HID);
        }
        asm volatile("barrier.cluster.wait.aligned;"   ::: "memory");
        buf ^= 1;
    }
}

// ======================= proj GEMM + bias + row L2-norm =================
__global__ void k_proj(const float* __restrict__ pb, float* __restrict__ out) {
    __shared__ float a_s[32][33];
    __shared__ float b_s[32][HID];
    int tid = threadIdx.x;
    int m0 = blockIdx.x * 32;
    int cg = tid & 31, rg = tid >> 5;
    float acc[4][8] = {};
    for (int kc = 0; kc < HID; kc += 32) {
        __syncthreads();
        for (int i = tid; i < 32 * 32; i += 256) {
            int r = i >> 5, c = i & 31;
            a_s[r][c] = g_hseq[(size_t)(m0 + r) * HID + kc + c];
        }
        for (int i = tid; i < 32 * HID; i += 256) {
            int r = i >> 8, c = i & 255;
            b_s[r][c] = g_wn[(size_t)(kc + r) * HID + c];
        }
        __syncthreads();
#pragma unroll 4
        for (int k = 0; k < 32; k++) {
            float a[4], bb[8];
#pragma unroll
            for (int i = 0; i < 4; i++) a[i] = a_s[rg * 4 + i][k];
#pragma unroll
            for (int j = 0; j < 8; j++) bb[j] = b_s[k][cg + 32 * j];
#pragma unroll
            for (int i = 0; i < 4; i++)
#pragma unroll
                for (int j = 0; j < 8; j++) acc[i][j] = fmaf(a[i], bb[j], acc[i][j]);
        }
    }
#pragma unroll
    for (int i = 0; i < 4; i++) {
        float ss = 0.f;
#pragma unroll
        for (int j = 0; j < 8; j++) {
            acc[i][j] += pb[cg + 32 * j];
            ss = fmaf(acc[i][j], acc[i][j], ss);
        }
        ss += __shfl_xor_sync(0xffffffffu, ss, 1);
        ss += __shfl_xor_sync(0xffffffffu, ss, 2);
        ss += __shfl_xor_sync(0xffffffffu, ss, 4);
        ss += __shfl_xor_sync(0xffffffffu, ss, 8);
        ss += __shfl_xor_sync(0xffffffffu, ss, 16);
        float nrm = sqrtf(ss);
        float sc = (nrm > 1e-6f) ? 1.0f / (nrm + 1e-8f) : 1.0f;
        size_t row = (size_t)(m0 + rg * 4 + i);
#pragma unroll
        for (int j = 0; j < 8; j++) out[row * HID + cg + 32 * j] = acc[i][j] * sc;
    }
}

// ======================= launcher =======================================
extern "C" void kernel_launch(void* const* d_in, const int* in_sizes, int n_in,
                              void* d_out, int out_size) {
    (void)in_sizes; (void)n_in; (void)out_size;
    const float* x   = (const float*)d_in[0];
    const float* c0w = (const float*)d_in[1];
    const float* c0b = (const float*)d_in[2];
    const float* r0s = (const float*)d_in[3];
    const float* c1w = (const float*)d_in[4];
    const float* c1b = (const float*)d_in[5];
    const float* r1s = (const float*)d_in[6];
    const float* c2w = (const float*)d_in[7];
    const float* c2b = (const float*)d_in[8];
    const float* r2s = (const float*)d_in[9];
    const float* wi  = (const float*)d_in[10];
    const float* bi  = (const float*)d_in[11];
    const float* wh  = (const float*)d_in[12];
    const float* bhn = (const float*)d_in[13];
    const float* pv  = (const float*)d_in[14];
    const float* pg  = (const float*)d_in[15];
    const float* pb  = (const float*)d_in[16];
    float* out = (float*)d_out;

    cudaFuncSetAttribute(k_gru, cudaFuncAttributeMaxDynamicSharedMemorySize, GRU_SMEM);
    cudaFuncSetAttribute(k_conv2, cudaFuncAttributeMaxDynamicSharedMemorySize, CONV2_SMEM);

    k_wnorm<<<1, 256>>>(pv, pg);
    k_conv0<<<dim3(8, BATCH), 256>>>(x, c0w, c0b, r0s);
    k_conv1<<<dim3(32, BATCH), 256>>>(c1w, c1b, r1s);
    k_conv2<<<dim3(8, BATCH), 256, CONV2_SMEM>>>(c2w, c2b, r2s);
    k_xi<<<dim3(1024, 12), 256>>>(wi, bi);
    k_gru<<<128, GRU_THREADS, GRU_SMEM>>>(wh, bhn);
    k_proj<<<2048, 256>>>(pb, out);
}